// round 1
// baseline (speedup 1.0000x reference)
#include <cuda_runtime.h>
#include <math.h>

#define NIMG 8
#define HH 36
#define WW 36
#define HWTOK 1296
#define HP 38
#define RCH 128
#define NHEAD 8
#define HEADC 16

// ---------------- scratch (device globals; zero-init at load) ----------------
__device__ float g_xtp[(size_t)NIMG*RCH*HP*HP];     // padded tanh(in-proj); borders stay 0
__device__ float g_za [(size_t)NIMG*256*HWTOK];     // [z | a]
__device__ float g_q  [(size_t)NIMG*RCH*HWTOK];
__device__ float g_k  [(size_t)NIMG*RCH*HWTOK];
__device__ float g_v  [(size_t)NIMG*RCH*HWTOK];
__device__ float g_h  [(size_t)NIMG*RCH*HWTOK];

// transposed weights ([in][out], coalesced for GEMM smem fills)
__device__ float g_wt_in [128*128];
__device__ float g_wt_q  [128*128];
__device__ float g_wt_k  [128*128];
__device__ float g_wt_v  [128*128];
__device__ float g_wt_out[128*128];
__device__ float g_wt_i  [256*128];
__device__ float g_wt_g  [256*128];
__device__ float g_wt_o  [256*128];
__device__ float g_wt_conv[1152*128];               // [(ci*9+tap)][o], ci<128 only

// ---------------- helpers ----------------
__device__ __forceinline__ float sigmoidf_(float x){ return 1.f/(1.f+expf(-x)); }

__device__ __forceinline__ unsigned long long pack2(float a, float b){
    unsigned long long r;
    asm("mov.b64 %0, {%1,%2};" : "=l"(r) : "f"(a), "f"(b));
    return r;
}
__device__ __forceinline__ void unpack2(unsigned long long v, float& a, float& b){
    asm("mov.b64 {%0,%1}, %2;" : "=f"(a), "=f"(b) : "l"(v));
}
__device__ __forceinline__ unsigned long long mul2(unsigned long long a, unsigned long long b){
    unsigned long long d;
    asm("mul.rn.f32x2 %0, %1, %2;" : "=l"(d) : "l"(a), "l"(b));
    return d;
}
__device__ __forceinline__ unsigned long long fma2r(unsigned long long a, unsigned long long b, unsigned long long c){
    unsigned long long d;
    asm("fma.rn.f32x2 %0, %1, %2, %3;" : "=l"(d) : "l"(a), "l"(b), "l"(c));
    return d;
}
__device__ __forceinline__ unsigned long long add2(unsigned long long a, unsigned long long b){
    unsigned long long d;
    asm("add.rn.f32x2 %0, %1, %2;" : "=l"(d) : "l"(a), "l"(b));
    return d;
}

// ---------------- weight repack ----------------
__global__ void repack_all(const float* __restrict__ w_in, const float* __restrict__ wq,
                           const float* __restrict__ wk,   const float* __restrict__ wv,
                           const float* __restrict__ w_i,  const float* __restrict__ w_g,
                           const float* __restrict__ w_o,  const float* __restrict__ w_out,
                           const float* __restrict__ w_conv)
{
    int idx = blockIdx.x*256 + threadIdx.x;
    if (idx < 5*16384) {
        int m = idx >> 14; int r = idx & 16383; int o = r >> 7; int i = r & 127;
        float v;
        if      (m==0) v = w_in[r];
        else if (m==1) v = wq[r];
        else if (m==2) v = wk[r];
        else if (m==3) v = wv[r];
        else           v = w_out[r];
        float* d = (m==0)?g_wt_in:(m==1)?g_wt_q:(m==2)?g_wt_k:(m==3)?g_wt_v:g_wt_out;
        d[i*128+o] = v;
    } else if (idx < 5*16384 + 3*32768) {
        int r = idx - 5*16384; int m = r >> 15; int rr = r & 32767;
        int o = rr >> 8; int i = rr & 255;    // src [128][256]
        float v = (m==0) ? w_i[rr] : (m==1) ? w_g[rr] : w_o[rr];
        float* d = (m==0)?g_wt_i:(m==1)?g_wt_g:g_wt_o;
        d[i*128+o] = v;
    } else if (idx < 5*16384 + 3*32768 + 147456) {
        int r = idx - (5*16384 + 3*32768);
        int o = r / 1152; int rem = r - o*1152;         // rem = ci*9+tap, ci<128
        g_wt_conv[rem*128 + o] = w_conv[(size_t)o*2304 + rem];
    }
}

// ---------------- generic 128-in GEMM over tokens ----------------
// MODE 0/1/2: q/k/v from g_za[:, :128]  (no bias)
// MODE 3:     in-proj from x -> g_xtp padded, tanh, bias
// MODE 4:     out-proj from g_h -> outx, bias
template<int MODE>
__global__ void gemm128_kernel(const float* __restrict__ inx,
                               const float* __restrict__ bias,
                               float* __restrict__ outx)
{
    __shared__ float xs[16][64];
    __shared__ float ws[16][128];
    const int n  = blockIdx.y;
    const int t0 = blockIdx.x * 64;
    const int tid = threadIdx.x;
    const int tt = tid & 15;       // token group (4 tokens)
    const int og = tid >> 4;       // out group (8 outs)

    const float* in; const float* wt; size_t ins;
    if      (MODE==0){ in=g_za; wt=g_wt_q;   ins=(size_t)256*HWTOK; }
    else if (MODE==1){ in=g_za; wt=g_wt_k;   ins=(size_t)256*HWTOK; }
    else if (MODE==2){ in=g_za; wt=g_wt_v;   ins=(size_t)256*HWTOK; }
    else if (MODE==3){ in=inx;  wt=g_wt_in;  ins=(size_t)128*HWTOK; }
    else             { in=g_h;  wt=g_wt_out; ins=(size_t)128*HWTOK; }

    const float* xn = in + (size_t)n * ins;
    float acc[8][4];
    #pragma unroll
    for (int o=0;o<8;o++){ acc[o][0]=acc[o][1]=acc[o][2]=acc[o][3]=0.f; }

    for (int kc=0; kc<128; kc+=16) {
        #pragma unroll
        for (int r=0;r<4;r++){
            int idx = tid + r*256; int i = idx >> 6; int t = idx & 63; int gt = t0 + t;
            xs[i][t] = (gt < HWTOK) ? xn[(size_t)(kc+i)*HWTOK + gt] : 0.f;
        }
        #pragma unroll
        for (int r=0;r<8;r++){
            int idx = tid + r*256; int i = idx >> 7; int o = idx & 127;
            ws[i][o] = wt[(kc+i)*128 + o];
        }
        __syncthreads();
        #pragma unroll
        for (int i=0;i<16;i++){
            float4 xv  = *(const float4*)&xs[i][tt*4];
            float4 wv0 = *(const float4*)&ws[i][og*8];
            float4 wv1 = *(const float4*)&ws[i][og*8+4];
            float wv[8] = {wv0.x,wv0.y,wv0.z,wv0.w,wv1.x,wv1.y,wv1.z,wv1.w};
            #pragma unroll
            for (int o=0;o<8;o++){
                acc[o][0] += wv[o]*xv.x;
                acc[o][1] += wv[o]*xv.y;
                acc[o][2] += wv[o]*xv.z;
                acc[o][3] += wv[o]*xv.w;
            }
        }
        __syncthreads();
    }
    #pragma unroll
    for (int o=0;o<8;o++){
        int oc = og*8+o;
        float bb = (MODE==3 || MODE==4) ? bias[oc] : 0.f;
        #pragma unroll
        for (int jj=0;jj<4;jj++){
            int gt = t0 + tt*4 + jj;
            if (gt >= HWTOK) continue;
            float v = acc[o][jj] + bb;
            if (MODE==3){
                int y = gt/WW, xc = gt - y*WW;
                g_xtp[(((size_t)n*RCH+oc)*HP + (y+1))*HP + (xc+1)] = tanhf(v);
            } else if (MODE==0) g_q[((size_t)n*RCH+oc)*HWTOK+gt] = v;
            else   if (MODE==1) g_k[((size_t)n*RCH+oc)*HWTOK+gt] = v;
            else   if (MODE==2) g_v[((size_t)n*RCH+oc)*HWTOK+gt] = v;
            else                outx[((size_t)n*RCH+oc)*HWTOK+gt] = v;
        }
    }
}

// ---------------- conv3x3 (padded input, 128 effective in-ch) ----------------
__global__ void conv3x3_kernel(const float* __restrict__ bias)
{
    __shared__ float xs[8][3][38];
    __shared__ float ws[8][9][128];
    const int n = blockIdx.y;
    const int y = blockIdx.x;                   // output row 0..35
    const int tid = threadIdx.x;                // 288 threads
    const int tg = tid % 9;                     // token group (4 cols)
    const int og = tid / 9;                     // out group (4 outs)
    float acc[4][4];
    #pragma unroll
    for (int o=0;o<4;o++) for (int t=0;t<4;t++) acc[o][t]=0.f;

    const float* xp = g_xtp + (size_t)n*RCH*HP*HP;
    for (int kc=0; kc<128; kc+=8) {
        for (int idx = tid; idx < 8*3*38; idx += 288) {
            int i = idx / 114; int rem = idx - i*114;
            int dy = rem / 38; int cx = rem - dy*38;
            xs[i][dy][cx] = xp[(size_t)(kc+i)*HP*HP + (y+dy)*HP + cx];
        }
        for (int idx = tid; idx < 9216; idx += 288)
            ((float*)ws)[idx] = g_wt_conv[(size_t)kc*1152 + idx];
        __syncthreads();
        #pragma unroll 2
        for (int i=0;i<8;i++){
            #pragma unroll
            for (int dy=0;dy<3;dy++){
                float xr[6];
                #pragma unroll
                for (int c=0;c<6;c++) xr[c] = xs[i][dy][tg*4+c];
                #pragma unroll
                for (int dx=0;dx<3;dx++){
                    float4 wv = *(const float4*)&ws[i][dy*3+dx][og*4];
                    float wa[4]={wv.x,wv.y,wv.z,wv.w};
                    #pragma unroll
                    for (int o=0;o<4;o++)
                        #pragma unroll
                        for (int t=0;t<4;t++)
                            acc[o][t] += wa[o]*xr[t+dx];
                }
            }
        }
        __syncthreads();
    }
    #pragma unroll
    for (int o=0;o<4;o++){
        int oc = og*4+o;
        float bb = bias[oc];
        #pragma unroll
        for (int t=0;t<4;t++){
            int xc = tg*4+t;
            g_za[((size_t)n*256 + oc)*HWTOK + y*WW + xc] = acc[o][t] + bb;
        }
    }
}

// ---------------- attention (per (n,head); K,V resident in smem) ----------------
#define QCHUNK 216
#define ATTN_THREADS 224
#define ATTN_SMEM (2*HWTOK*HEADC*4)

__global__ void attn_kernel()
{
    extern __shared__ float sm[];
    float* Ks = sm;                       // [1296][16]
    float* Vs = sm + HWTOK*HEADC;
    const int nh = blockIdx.y; const int n = nh >> 3; const int h = nh & 7;
    const int tid = threadIdx.x;
    const float* kp = g_k + ((size_t)n*RCH + h*HEADC)*HWTOK;
    const float* vp = g_v + ((size_t)n*RCH + h*HEADC)*HWTOK;
    #pragma unroll
    for (int c=0;c<HEADC;c++){
        for (int j=tid;j<HWTOK;j+=ATTN_THREADS){
            Ks[j*HEADC+c] = kp[(size_t)c*HWTOK+j];
            Vs[j*HEADC+c] = vp[(size_t)c*HWTOK+j];
        }
    }
    __syncthreads();
    if (tid < QCHUNK){
        const int q = blockIdx.x*QCHUNK + tid;
        const float* qp = g_q + ((size_t)n*RCH + h*HEADC)*HWTOK;
        unsigned long long q2[8], a2[8];
        #pragma unroll
        for (int p=0;p<8;p++){
            q2[p] = pack2(qp[(size_t)(2*p)*HWTOK+q], qp[(size_t)(2*p+1)*HWTOK+q]);
            a2[p] = pack2(0.f,0.f);
        }
        float l = 0.f;
        #pragma unroll 2
        for (int j=0;j<HWTOK;j++){
            const unsigned long long* k8 = (const unsigned long long*)(Ks + j*HEADC);
            unsigned long long sA = mul2(q2[0], k8[0]);
            unsigned long long sB = mul2(q2[1], k8[1]);
            sA = fma2r(q2[2], k8[2], sA);
            sB = fma2r(q2[3], k8[3], sB);
            sA = fma2r(q2[4], k8[4], sA);
            sB = fma2r(q2[5], k8[5], sB);
            sA = fma2r(q2[6], k8[6], sA);
            sB = fma2r(q2[7], k8[7], sB);
            sA = add2(sA, sB);
            float slo, shi; unpack2(sA, slo, shi);
            float e = __expf(slo + shi);
            l += e;
            unsigned long long eb = pack2(e, e);
            const unsigned long long* v8 = (const unsigned long long*)(Vs + j*HEADC);
            #pragma unroll
            for (int p=0;p<8;p++) a2[p] = fma2r(eb, v8[p], a2[p]);
        }
        float inv = 1.f / l;
        float* ap = g_za + ((size_t)n*256 + 128 + h*HEADC)*HWTOK + q;
        #pragma unroll
        for (int p=0;p<8;p++){
            float lo, hi; unpack2(a2[p], lo, hi);
            ap[(size_t)(2*p)*HWTOK]   = lo*inv;
            ap[(size_t)(2*p+1)*HWTOK] = hi*inv;
        }
    }
}

// ---------------- fused gates i/g/o -> h  (f*c0 == 0, f skipped) ----------------
__global__ void gates_kernel(const float* __restrict__ bi,
                             const float* __restrict__ bg,
                             const float* __restrict__ bo)
{
    __shared__ float xs [16][32];
    __shared__ float wsi[16][128];
    __shared__ float wsg[16][128];
    __shared__ float wso[16][128];
    const int n = blockIdx.y;
    const int t0 = blockIdx.x*32;
    const int tid = threadIdx.x;
    const int tt = tid & 7;      // 8 token groups x 4
    const int og = tid >> 3;     // 32 out groups x 4
    float ai[4][4], ag[4][4], ao[4][4];
    #pragma unroll
    for (int o=0;o<4;o++) for (int t=0;t<4;t++){ ai[o][t]=0.f; ag[o][t]=0.f; ao[o][t]=0.f; }

    const float* in = g_za + (size_t)n*256*HWTOK;
    for (int kc=0; kc<256; kc+=16) {
        #pragma unroll
        for (int r=0;r<2;r++){
            int idx = tid + r*256; int i = idx >> 5; int t = idx & 31; int gt = t0+t;
            xs[i][t] = (gt < HWTOK) ? in[(size_t)(kc+i)*HWTOK + gt] : 0.f;
        }
        #pragma unroll
        for (int r=0;r<8;r++){
            int idx = tid + r*256; int i = idx >> 7; int o = idx & 127;
            wsi[i][o] = g_wt_i[(kc+i)*128+o];
            wsg[i][o] = g_wt_g[(kc+i)*128+o];
            wso[i][o] = g_wt_o[(kc+i)*128+o];
        }
        __syncthreads();
        #pragma unroll
        for (int i=0;i<16;i++){
            float4 xv  = *(const float4*)&xs[i][tt*4];
            float xa[4] = {xv.x,xv.y,xv.z,xv.w};
            float4 wi4 = *(const float4*)&wsi[i][og*4];
            float4 wg4 = *(const float4*)&wsg[i][og*4];
            float4 wo4 = *(const float4*)&wso[i][og*4];
            float wia[4]={wi4.x,wi4.y,wi4.z,wi4.w};
            float wga[4]={wg4.x,wg4.y,wg4.z,wg4.w};
            float woa[4]={wo4.x,wo4.y,wo4.z,wo4.w};
            #pragma unroll
            for (int o=0;o<4;o++)
                #pragma unroll
                for (int t=0;t<4;t++){
                    ai[o][t] += wia[o]*xa[t];
                    ag[o][t] += wga[o]*xa[t];
                    ao[o][t] += woa[o]*xa[t];
                }
        }
        __syncthreads();
    }
    #pragma unroll
    for (int o=0;o<4;o++){
        int oc = og*4+o;
        float bbi = bi[oc], bbg = bg[oc], bbo = bo[oc];
        #pragma unroll
        for (int t=0;t<4;t++){
            int gt = t0 + tt*4 + t;
            if (gt >= HWTOK) continue;
            float iv = sigmoidf_(ai[o][t] + bbi);
            float gv = tanhf(ag[o][t] + bbg);
            float ov = sigmoidf_(ao[o][t] + bbo);
            float c  = iv * gv;          // f * c0 == 0
            g_h[((size_t)n*RCH + oc)*HWTOK + gt] = ov * tanhf(c);
        }
    }
}

// ---------------- launch ----------------
extern "C" void kernel_launch(void* const* d_in, const int* in_sizes, int n_in,
                              void* d_out, int out_size)
{
    const float* x      = (const float*)d_in[0];
    const float* w_in   = (const float*)d_in[1];
    const float* b_in   = (const float*)d_in[2];
    const float* w_conv = (const float*)d_in[3];
    const float* b_conv = (const float*)d_in[4];
    const float* wq     = (const float*)d_in[5];
    const float* wk     = (const float*)d_in[6];
    const float* wv     = (const float*)d_in[7];
    const float* w_i    = (const float*)d_in[8];
    const float* b_i    = (const float*)d_in[9];
    // d_in[10], d_in[11]: w_f/b_f unused (first timestep: f*c0 == 0)
    const float* w_g    = (const float*)d_in[12];
    const float* b_g    = (const float*)d_in[13];
    const float* w_o    = (const float*)d_in[14];
    const float* b_o    = (const float*)d_in[15];
    const float* w_out  = (const float*)d_in[16];
    const float* b_out  = (const float*)d_in[17];
    float* out = (float*)d_out;

    cudaFuncSetAttribute(attn_kernel, cudaFuncAttributeMaxDynamicSharedMemorySize, ATTN_SMEM);

    repack_all<<<1280,256>>>(w_in, wq, wk, wv, w_i, w_g, w_o, w_out, w_conv);

    dim3 g21(21, NIMG);
    gemm128_kernel<3><<<g21,256>>>(x, b_in, nullptr);          // in-proj -> g_xtp (padded, tanh)
    conv3x3_kernel<<<dim3(36,NIMG),288>>>(b_conv);             // -> g_za[:, :128]
    gemm128_kernel<0><<<g21,256>>>(nullptr, nullptr, nullptr); // q
    gemm128_kernel<1><<<g21,256>>>(nullptr, nullptr, nullptr); // k
    gemm128_kernel<2><<<g21,256>>>(nullptr, nullptr, nullptr); // v
    attn_kernel<<<dim3(HWTOK/QCHUNK, NIMG*NHEAD), ATTN_THREADS, ATTN_SMEM>>>(); // -> g_za[:,128:]
    gates_kernel<<<dim3(41,NIMG),256>>>(b_i, b_g, b_o);        // -> g_h
    gemm128_kernel<4><<<g21,256>>>(nullptr, b_out, out);       // out-proj -> d_out
}

// round 2
// speedup vs baseline: 1.1024x; 1.1024x over previous
#include <cuda_runtime.h>
#include <math.h>

#define NIMG 8
#define HH 36
#define WW 36
#define HWTOK 1296
#define HP 38
#define RCH 128
#define NHEAD 8
#define HEADC 16

typedef unsigned long long ull;

// ---------------- scratch (device globals; zero-init at load) ----------------
__device__ float g_xtp[(size_t)NIMG*RCH*HP*HP];     // padded tanh(in-proj); borders stay 0
__device__ float g_za [(size_t)NIMG*256*HWTOK];     // [z | a]
__device__ float g_q  [(size_t)NIMG*RCH*HWTOK];
__device__ float g_k  [(size_t)NIMG*RCH*HWTOK];
__device__ float g_v  [(size_t)NIMG*RCH*HWTOK];
__device__ float g_h  [(size_t)NIMG*RCH*HWTOK];

// transposed weights ([in][out], coalesced for GEMM smem fills)
__device__ float g_wt_in [128*128];
__device__ float g_wt_q  [128*128];
__device__ float g_wt_k  [128*128];
__device__ float g_wt_v  [128*128];
__device__ float g_wt_out[128*128];
__device__ float g_wt_i  [256*128];
__device__ float g_wt_g  [256*128];
__device__ float g_wt_o  [256*128];
__device__ float g_wt_conv[1152*128];               // [(ci*9+tap)][o], ci<128 only

// ---------------- helpers ----------------
__device__ __forceinline__ float tanh_fast(float x){
    float r; asm("tanh.approx.f32 %0, %1;" : "=f"(r) : "f"(x)); return r;
}
__device__ __forceinline__ float sigmoid_fast(float x){
    return 0.5f * tanh_fast(0.5f * x) + 0.5f;
}
__device__ __forceinline__ ull pack2(float a, float b){
    ull r; asm("mov.b64 %0, {%1,%2};" : "=l"(r) : "f"(a), "f"(b)); return r;
}
__device__ __forceinline__ ull pack1(float a){
    ull r; asm("mov.b64 %0, {%1,%1};" : "=l"(r) : "f"(a)); return r;
}
__device__ __forceinline__ void unpack2(ull v, float& a, float& b){
    asm("mov.b64 {%0,%1}, %2;" : "=f"(a), "=f"(b) : "l"(v));
}
__device__ __forceinline__ ull mul2(ull a, ull b){
    ull d; asm("mul.rn.f32x2 %0, %1, %2;" : "=l"(d) : "l"(a), "l"(b)); return d;
}
__device__ __forceinline__ ull fma2r(ull a, ull b, ull c){
    ull d; asm("fma.rn.f32x2 %0, %1, %2, %3;" : "=l"(d) : "l"(a), "l"(b), "l"(c)); return d;
}
__device__ __forceinline__ ull add2(ull a, ull b){
    ull d; asm("add.rn.f32x2 %0, %1, %2;" : "=l"(d) : "l"(a), "l"(b)); return d;
}

// ---------------- weight repack ----------------
__global__ void repack_all(const float* __restrict__ w_in, const float* __restrict__ wq,
                           const float* __restrict__ wk,   const float* __restrict__ wv,
                           const float* __restrict__ w_i,  const float* __restrict__ w_g,
                           const float* __restrict__ w_o,  const float* __restrict__ w_out,
                           const float* __restrict__ w_conv)
{
    int idx = blockIdx.x*256 + threadIdx.x;
    if (idx < 5*16384) {
        int m = idx >> 14; int r = idx & 16383; int o = r >> 7; int i = r & 127;
        float v;
        if      (m==0) v = w_in[r];
        else if (m==1) v = wq[r];
        else if (m==2) v = wk[r];
        else if (m==3) v = wv[r];
        else           v = w_out[r];
        float* d = (m==0)?g_wt_in:(m==1)?g_wt_q:(m==2)?g_wt_k:(m==3)?g_wt_v:g_wt_out;
        d[i*128+o] = v;
    } else if (idx < 5*16384 + 3*32768) {
        int r = idx - 5*16384; int m = r >> 15; int rr = r & 32767;
        int o = rr >> 8; int i = rr & 255;    // src [128][256]
        float v = (m==0) ? w_i[rr] : (m==1) ? w_g[rr] : w_o[rr];
        float* d = (m==0)?g_wt_i:(m==1)?g_wt_g:g_wt_o;
        d[i*128+o] = v;
    } else if (idx < 5*16384 + 3*32768 + 147456) {
        int r = idx - (5*16384 + 3*32768);
        int o = r / 1152; int rem = r - o*1152;         // rem = ci*9+tap, ci<128
        g_wt_conv[rem*128 + o] = w_conv[(size_t)o*2304 + rem];
    }
}

// ---------------- in/out 128-in GEMM over tokens (f32x2, o-paired) ----------------
// MODE 3: in-proj from x -> g_xtp padded, tanh, bias
// MODE 4: out-proj from g_h -> outx, bias
template<int MODE>
__global__ void gemm128_kernel(const float* __restrict__ inx,
                               const float* __restrict__ bias,
                               float* __restrict__ outx)
{
    __shared__ float xs[16][64];
    __shared__ float ws[16][128];
    const int n  = blockIdx.y;
    const int t0 = blockIdx.x * 64;
    const int tid = threadIdx.x;
    const int tt = tid & 15;       // token group (4 tokens)
    const int og = tid >> 4;       // out group (8 outs = 4 o-pairs)

    const float* in = (MODE==3) ? inx : g_h;
    const float* wt = (MODE==3) ? g_wt_in : g_wt_out;
    const float* xn = in + (size_t)n * 128 * HWTOK;

    ull acc2[4][4];   // [opair][token]
    #pragma unroll
    for (int p=0;p<4;p++) for (int t=0;t<4;t++) acc2[p][t] = 0ull;

    for (int kc=0; kc<128; kc+=16) {
        #pragma unroll
        for (int r=0;r<4;r++){
            int idx = tid + r*256; int i = idx >> 6; int t = idx & 63; int gt = t0 + t;
            xs[i][t] = (gt < HWTOK) ? xn[(size_t)(kc+i)*HWTOK + gt] : 0.f;
        }
        #pragma unroll
        for (int r=0;r<8;r++){
            int idx = tid + r*256; int i = idx >> 7; int o = idx & 127;
            ws[i][o] = wt[(kc+i)*128 + o];
        }
        __syncthreads();
        #pragma unroll
        for (int i=0;i<16;i++){
            float4 xv  = *(const float4*)&xs[i][tt*4];
            ull xb[4] = {pack1(xv.x), pack1(xv.y), pack1(xv.z), pack1(xv.w)};
            float4 wv0 = *(const float4*)&ws[i][og*8];
            float4 wv1 = *(const float4*)&ws[i][og*8+4];
            ull wp[4] = {pack2(wv0.x,wv0.y), pack2(wv0.z,wv0.w),
                         pack2(wv1.x,wv1.y), pack2(wv1.z,wv1.w)};
            #pragma unroll
            for (int p=0;p<4;p++)
                #pragma unroll
                for (int t=0;t<4;t++)
                    acc2[p][t] = fma2r(xb[t], wp[p], acc2[p][t]);
        }
        __syncthreads();
    }
    #pragma unroll
    for (int p=0;p<4;p++){
        int oc0 = og*8 + 2*p;
        float b0 = bias[oc0], b1 = bias[oc0+1];
        #pragma unroll
        for (int t=0;t<4;t++){
            int gt = t0 + tt*4 + t;
            if (gt >= HWTOK) continue;
            float v0, v1; unpack2(acc2[p][t], v0, v1);
            v0 += b0; v1 += b1;
            if (MODE==3){
                int y = gt/WW, xc = gt - y*WW;
                size_t base = (((size_t)n*RCH)*HP + (y+1))*HP + (xc+1);
                g_xtp[base + (size_t)oc0*HP*HP]     = tanh_fast(v0);
                g_xtp[base + (size_t)(oc0+1)*HP*HP] = tanh_fast(v1);
            } else {
                outx[((size_t)n*RCH+oc0)*HWTOK+gt]     = v0;
                outx[((size_t)n*RCH+oc0+1)*HWTOK+gt]   = v1;
            }
        }
    }
}

// ---------------- fused q/k/v GEMM (3 mats share x tile) ----------------
__global__ void qkv_kernel()
{
    __shared__ float xs [16][32];
    __shared__ float wsq[16][128];
    __shared__ float wsk[16][128];
    __shared__ float wsv[16][128];
    const int n = blockIdx.y;
    const int t0 = blockIdx.x*32;
    const int tid = threadIdx.x;
    const int tt = tid & 7;      // 8 token groups x 4
    const int og = tid >> 3;     // 32 out groups x 4 (2 o-pairs)

    ull acc2[3][2][4];
    #pragma unroll
    for (int m=0;m<3;m++) for (int p=0;p<2;p++) for (int t=0;t<4;t++) acc2[m][p][t]=0ull;

    const float* in = g_za + (size_t)n*256*HWTOK;   // z region (first 128 ch)
    for (int kc=0; kc<128; kc+=16) {
        #pragma unroll
        for (int r=0;r<2;r++){
            int idx = tid + r*256; int i = idx >> 5; int t = idx & 31; int gt = t0+t;
            xs[i][t] = (gt < HWTOK) ? in[(size_t)(kc+i)*HWTOK + gt] : 0.f;
        }
        #pragma unroll
        for (int r=0;r<8;r++){
            int idx = tid + r*256; int i = idx >> 7; int o = idx & 127;
            wsq[i][o] = g_wt_q[(kc+i)*128+o];
            wsk[i][o] = g_wt_k[(kc+i)*128+o];
            wsv[i][o] = g_wt_v[(kc+i)*128+o];
        }
        __syncthreads();
        #pragma unroll
        for (int i=0;i<16;i++){
            float4 xv = *(const float4*)&xs[i][tt*4];
            ull xb[4] = {pack1(xv.x), pack1(xv.y), pack1(xv.z), pack1(xv.w)};
            float4 wq4 = *(const float4*)&wsq[i][og*4];
            float4 wk4 = *(const float4*)&wsk[i][og*4];
            float4 wv4 = *(const float4*)&wsv[i][og*4];
            ull wpq[2] = {pack2(wq4.x,wq4.y), pack2(wq4.z,wq4.w)};
            ull wpk[2] = {pack2(wk4.x,wk4.y), pack2(wk4.z,wk4.w)};
            ull wpv[2] = {pack2(wv4.x,wv4.y), pack2(wv4.z,wv4.w)};
            #pragma unroll
            for (int p=0;p<2;p++)
                #pragma unroll
                for (int t=0;t<4;t++){
                    acc2[0][p][t] = fma2r(xb[t], wpq[p], acc2[0][p][t]);
                    acc2[1][p][t] = fma2r(xb[t], wpk[p], acc2[1][p][t]);
                    acc2[2][p][t] = fma2r(xb[t], wpv[p], acc2[2][p][t]);
                }
        }
        __syncthreads();
    }
    #pragma unroll
    for (int m=0;m<3;m++){
        float* dst = (m==0)?g_q:(m==1)?g_k:g_v;
        #pragma unroll
        for (int p=0;p<2;p++){
            int oc0 = og*4 + 2*p;
            #pragma unroll
            for (int t=0;t<4;t++){
                int gt = t0 + tt*4 + t;
                if (gt >= HWTOK) continue;
                float v0, v1; unpack2(acc2[m][p][t], v0, v1);
                dst[((size_t)n*RCH+oc0)*HWTOK+gt]   = v0;
                dst[((size_t)n*RCH+oc0+1)*HWTOK+gt] = v1;
            }
        }
    }
}

// ---------------- conv3x3 (padded input, 128 effective in-ch, f32x2) ----------------
__global__ void conv3x3_kernel(const float* __restrict__ bias)
{
    __shared__ float xs[8][3][38];
    __shared__ float ws[8][9][128];
    const int n = blockIdx.y;
    const int y = blockIdx.x;                   // output row 0..35
    const int tid = threadIdx.x;                // 288 threads
    const int tg = tid % 9;                     // token group (4 cols)
    const int og = tid / 9;                     // out group (4 outs = 2 o-pairs)
    ull acc2[2][4];
    #pragma unroll
    for (int p=0;p<2;p++) for (int t=0;t<4;t++) acc2[p][t]=0ull;

    const float* xp = g_xtp + (size_t)n*RCH*HP*HP;
    for (int kc=0; kc<128; kc+=8) {
        for (int idx = tid; idx < 8*3*38; idx += 288) {
            int i = idx / 114; int rem = idx - i*114;
            int dy = rem / 38; int cx = rem - dy*38;
            xs[i][dy][cx] = xp[(size_t)(kc+i)*HP*HP + (y+dy)*HP + cx];
        }
        for (int idx = tid; idx < 9216; idx += 288)
            ((float*)ws)[idx] = g_wt_conv[(size_t)kc*1152 + idx];
        __syncthreads();
        #pragma unroll 2
        for (int i=0;i<8;i++){
            #pragma unroll
            for (int dy=0;dy<3;dy++){
                ull xb[6];
                #pragma unroll
                for (int c=0;c<6;c++) xb[c] = pack1(xs[i][dy][tg*4+c]);
                #pragma unroll
                for (int dx=0;dx<3;dx++){
                    float4 wv = *(const float4*)&ws[i][dy*3+dx][og*4];
                    ull wp0 = pack2(wv.x,wv.y), wp1 = pack2(wv.z,wv.w);
                    #pragma unroll
                    for (int t=0;t<4;t++){
                        acc2[0][t] = fma2r(xb[t+dx], wp0, acc2[0][t]);
                        acc2[1][t] = fma2r(xb[t+dx], wp1, acc2[1][t]);
                    }
                }
            }
        }
        __syncthreads();
    }
    #pragma unroll
    for (int p=0;p<2;p++){
        int oc0 = og*4 + 2*p;
        float b0 = bias[oc0], b1 = bias[oc0+1];
        #pragma unroll
        for (int t=0;t<4;t++){
            int xc = tg*4+t;
            float v0, v1; unpack2(acc2[p][t], v0, v1);
            g_za[((size_t)n*256 + oc0)*HWTOK + y*WW + xc]   = v0 + b0;
            g_za[((size_t)n*256 + oc0+1)*HWTOK + y*WW + xc] = v1 + b1;
        }
    }
}

// ---------------- attention: K,V smem-resident, 2 q per thread ----------------
#define ATTN_THREADS 224
#define QCHUNK (2*ATTN_THREADS)
#define ATTN_SMEM (2*HWTOK*HEADC*4)

__global__ void attn_kernel()
{
    extern __shared__ float sm[];
    float* Ks = sm;                       // [1296][16]
    float* Vs = sm + HWTOK*HEADC;
    const int nh = blockIdx.y; const int n = nh >> 3; const int h = nh & 7;
    const int tid = threadIdx.x;
    const float* kp = g_k + ((size_t)n*RCH + h*HEADC)*HWTOK;
    const float* vp = g_v + ((size_t)n*RCH + h*HEADC)*HWTOK;
    #pragma unroll
    for (int c=0;c<HEADC;c++){
        for (int j=tid;j<HWTOK;j+=ATTN_THREADS){
            Ks[j*HEADC+c] = kp[(size_t)c*HWTOK+j];
            Vs[j*HEADC+c] = vp[(size_t)c*HWTOK+j];
        }
    }
    __syncthreads();

    const int qa = blockIdx.x*QCHUNK + tid;
    int qb = qa + ATTN_THREADS;
    const bool hasB = (qb < HWTOK);
    if (!hasB) qb = HWTOK-1;

    const float* qp = g_q + ((size_t)n*RCH + h*HEADC)*HWTOK;
    ull q2a[8], q2b[8], a2a[8], a2b[8];
    #pragma unroll
    for (int p=0;p<8;p++){
        q2a[p] = pack2(qp[(size_t)(2*p)*HWTOK+qa], qp[(size_t)(2*p+1)*HWTOK+qa]);
        q2b[p] = pack2(qp[(size_t)(2*p)*HWTOK+qb], qp[(size_t)(2*p+1)*HWTOK+qb]);
        a2a[p] = 0ull; a2b[p] = 0ull;
    }
    float la = 0.f, lb = 0.f;
    #pragma unroll 2
    for (int j=0;j<HWTOK;j++){
        const float4* kr = (const float4*)(Ks + j*HEADC);
        float4 k0 = kr[0], k1 = kr[1], k2 = kr[2], k3 = kr[3];
        ull kk[8] = {pack2(k0.x,k0.y), pack2(k0.z,k0.w),
                     pack2(k1.x,k1.y), pack2(k1.z,k1.w),
                     pack2(k2.x,k2.y), pack2(k2.z,k2.w),
                     pack2(k3.x,k3.y), pack2(k3.z,k3.w)};
        ull sA = mul2(q2a[0], kk[0]);
        ull sB = mul2(q2a[1], kk[1]);
        ull tA = mul2(q2b[0], kk[0]);
        ull tB = mul2(q2b[1], kk[1]);
        #pragma unroll
        for (int p=2;p<8;p+=2){
            sA = fma2r(q2a[p],   kk[p],   sA);
            sB = fma2r(q2a[p+1], kk[p+1], sB);
            tA = fma2r(q2b[p],   kk[p],   tA);
            tB = fma2r(q2b[p+1], kk[p+1], tB);
        }
        sA = add2(sA, sB);
        tA = add2(tA, tB);
        float s0, s1, t0, t1;
        unpack2(sA, s0, s1); unpack2(tA, t0, t1);
        float ea = __expf(s0 + s1);
        float eb = __expf(t0 + t1);
        la += ea; lb += eb;
        ull ea2 = pack1(ea), eb2 = pack1(eb);
        const float4* vr = (const float4*)(Vs + j*HEADC);
        float4 v0 = vr[0], v1 = vr[1], v2 = vr[2], v3 = vr[3];
        ull vv[8] = {pack2(v0.x,v0.y), pack2(v0.z,v0.w),
                     pack2(v1.x,v1.y), pack2(v1.z,v1.w),
                     pack2(v2.x,v2.y), pack2(v2.z,v2.w),
                     pack2(v3.x,v3.y), pack2(v3.z,v3.w)};
        #pragma unroll
        for (int p=0;p<8;p++){
            a2a[p] = fma2r(ea2, vv[p], a2a[p]);
            a2b[p] = fma2r(eb2, vv[p], a2b[p]);
        }
    }
    float inva = 1.f / la;
    float* ap = g_za + ((size_t)n*256 + 128 + h*HEADC)*HWTOK;
    #pragma unroll
    for (int p=0;p<8;p++){
        float lo, hi; unpack2(a2a[p], lo, hi);
        ap[(size_t)(2*p)*HWTOK + qa]   = lo*inva;
        ap[(size_t)(2*p+1)*HWTOK + qa] = hi*inva;
    }
    if (hasB){
        float invb = 1.f / lb;
        #pragma unroll
        for (int p=0;p<8;p++){
            float lo, hi; unpack2(a2b[p], lo, hi);
            ap[(size_t)(2*p)*HWTOK + qb]   = lo*invb;
            ap[(size_t)(2*p+1)*HWTOK + qb] = hi*invb;
        }
    }
}

// ---------------- fused gates i/g/o -> h  (f*c0 == 0, f skipped) ----------------
__global__ void gates_kernel(const float* __restrict__ bi,
                             const float* __restrict__ bg,
                             const float* __restrict__ bo)
{
    __shared__ float xs [16][32];
    __shared__ float wsi[16][128];
    __shared__ float wsg[16][128];
    __shared__ float wso[16][128];
    const int n = blockIdx.y;
    const int t0 = blockIdx.x*32;
    const int tid = threadIdx.x;
    const int tt = tid & 7;      // 8 token groups x 4
    const int og = tid >> 3;     // 32 out groups x 4 (2 o-pairs)
    ull ai[2][4], ag[2][4], ao[2][4];
    #pragma unroll
    for (int p=0;p<2;p++) for (int t=0;t<4;t++){ ai[p][t]=0ull; ag[p][t]=0ull; ao[p][t]=0ull; }

    const float* in = g_za + (size_t)n*256*HWTOK;
    for (int kc=0; kc<256; kc+=16) {
        #pragma unroll
        for (int r=0;r<2;r++){
            int idx = tid + r*256; int i = idx >> 5; int t = idx & 31; int gt = t0+t;
            xs[i][t] = (gt < HWTOK) ? in[(size_t)(kc+i)*HWTOK + gt] : 0.f;
        }
        #pragma unroll
        for (int r=0;r<8;r++){
            int idx = tid + r*256; int i = idx >> 7; int o = idx & 127;
            wsi[i][o] = g_wt_i[(kc+i)*128+o];
            wsg[i][o] = g_wt_g[(kc+i)*128+o];
            wso[i][o] = g_wt_o[(kc+i)*128+o];
        }
        __syncthreads();
        #pragma unroll
        for (int i=0;i<16;i++){
            float4 xv  = *(const float4*)&xs[i][tt*4];
            ull xb[4] = {pack1(xv.x), pack1(xv.y), pack1(xv.z), pack1(xv.w)};
            float4 wi4 = *(const float4*)&wsi[i][og*4];
            float4 wg4 = *(const float4*)&wsg[i][og*4];
            float4 wo4 = *(const float4*)&wso[i][og*4];
            ull wpi[2] = {pack2(wi4.x,wi4.y), pack2(wi4.z,wi4.w)};
            ull wpg[2] = {pack2(wg4.x,wg4.y), pack2(wg4.z,wg4.w)};
            ull wpo[2] = {pack2(wo4.x,wo4.y), pack2(wo4.z,wo4.w)};
            #pragma unroll
            for (int p=0;p<2;p++)
                #pragma unroll
                for (int t=0;t<4;t++){
                    ai[p][t] = fma2r(xb[t], wpi[p], ai[p][t]);
                    ag[p][t] = fma2r(xb[t], wpg[p], ag[p][t]);
                    ao[p][t] = fma2r(xb[t], wpo[p], ao[p][t]);
                }
        }
        __syncthreads();
    }
    #pragma unroll
    for (int p=0;p<2;p++){
        int oc0 = og*4 + 2*p;
        float bi0 = bi[oc0], bi1 = bi[oc0+1];
        float bg0 = bg[oc0], bg1 = bg[oc0+1];
        float bo0 = bo[oc0], bo1 = bo[oc0+1];
        #pragma unroll
        for (int t=0;t<4;t++){
            int gt = t0 + tt*4 + t;
            if (gt >= HWTOK) continue;
            float i0, i1, g0, g1, o0, o1;
            unpack2(ai[p][t], i0, i1);
            unpack2(ag[p][t], g0, g1);
            unpack2(ao[p][t], o0, o1);
            float iv0 = sigmoid_fast(i0 + bi0), iv1 = sigmoid_fast(i1 + bi1);
            float gv0 = tanh_fast(g0 + bg0),    gv1 = tanh_fast(g1 + bg1);
            float ov0 = sigmoid_fast(o0 + bo0), ov1 = sigmoid_fast(o1 + bo1);
            g_h[((size_t)n*RCH + oc0)*HWTOK + gt]   = ov0 * tanh_fast(iv0 * gv0);
            g_h[((size_t)n*RCH + oc0+1)*HWTOK + gt] = ov1 * tanh_fast(iv1 * gv1);
        }
    }
}

// ---------------- launch ----------------
extern "C" void kernel_launch(void* const* d_in, const int* in_sizes, int n_in,
                              void* d_out, int out_size)
{
    const float* x      = (const float*)d_in[0];
    const float* w_in   = (const float*)d_in[1];
    const float* b_in   = (const float*)d_in[2];
    const float* w_conv = (const float*)d_in[3];
    const float* b_conv = (const float*)d_in[4];
    const float* wq     = (const float*)d_in[5];
    const float* wk     = (const float*)d_in[6];
    const float* wv     = (const float*)d_in[7];
    const float* w_i    = (const float*)d_in[8];
    const float* b_i    = (const float*)d_in[9];
    // d_in[10], d_in[11]: w_f/b_f unused (first timestep: f*c0 == 0)
    const float* w_g    = (const float*)d_in[12];
    const float* b_g    = (const float*)d_in[13];
    const float* w_o    = (const float*)d_in[14];
    const float* b_o    = (const float*)d_in[15];
    const float* w_out  = (const float*)d_in[16];
    const float* b_out  = (const float*)d_in[17];
    float* out = (float*)d_out;

    cudaFuncSetAttribute(attn_kernel, cudaFuncAttributeMaxDynamicSharedMemorySize, ATTN_SMEM);

    repack_all<<<1280,256>>>(w_in, wq, wk, wv, w_i, w_g, w_o, w_out, w_conv);

    dim3 g21(21, NIMG);
    gemm128_kernel<3><<<g21,256>>>(x, b_in, nullptr);          // in-proj -> g_xtp (padded, tanh)
    conv3x3_kernel<<<dim3(36,NIMG),288>>>(b_conv);             // -> g_za[:, :128]
    qkv_kernel<<<dim3(41,NIMG),256>>>();                       // q,k,v in one pass
    attn_kernel<<<dim3(3, NIMG*NHEAD), ATTN_THREADS, ATTN_SMEM>>>(); // -> g_za[:,128:]
    gates_kernel<<<dim3(41,NIMG),256>>>(b_i, b_g, b_o);        // -> g_h
    gemm128_kernel<4><<<g21,256>>>(nullptr, b_out, out);       // out-proj -> d_out
}

// round 3
// speedup vs baseline: 1.5538x; 1.4095x over previous
#include <cuda_runtime.h>
#include <math.h>

#define NIMG 8
#define HH 36
#define WW 36
#define HWTOK 1296
#define HP 38
#define RCH 128
#define NHEAD 8
#define HEADC 16
#define LOG2E 1.44269504088896340736f

typedef unsigned long long ull;

// ---------------- scratch (device globals; zero-init at load) ----------------
__device__ float g_xtp[(size_t)NIMG*RCH*HP*HP];     // padded tanh(in-proj); borders stay 0
__device__ float g_za [(size_t)NIMG*256*HWTOK];     // [z | a]
__device__ float g_q  [(size_t)NIMG*RCH*HWTOK];
__device__ float g_k  [(size_t)NIMG*RCH*HWTOK];
__device__ float g_v  [(size_t)NIMG*RCH*HWTOK];
__device__ float g_h  [(size_t)NIMG*RCH*HWTOK];

// transposed weights ([in][out], coalesced for GEMM smem fills)
__device__ float g_wt_in [128*128];
__device__ float g_wt_q  [128*128];
__device__ float g_wt_k  [128*128];
__device__ float g_wt_v  [128*128];
__device__ float g_wt_out[128*128];
__device__ float g_wt_i  [256*128];
__device__ float g_wt_g  [256*128];
__device__ float g_wt_o  [256*128];
__device__ float g_wt_conv[1152*128];               // [(ci*9+tap)][o], ci<128 only

// ---------------- helpers ----------------
__device__ __forceinline__ float tanh_fast(float x){
    float r; asm("tanh.approx.f32 %0, %1;" : "=f"(r) : "f"(x)); return r;
}
__device__ __forceinline__ float sigmoid_fast(float x){
    return 0.5f * tanh_fast(0.5f * x) + 0.5f;
}
__device__ __forceinline__ float ex2_fast(float x){
    float r; asm("ex2.approx.f32 %0, %1;" : "=f"(r) : "f"(x)); return r;
}
__device__ __forceinline__ ull pack2(float a, float b){
    ull r; asm("mov.b64 %0, {%1,%2};" : "=l"(r) : "f"(a), "f"(b)); return r;
}
__device__ __forceinline__ ull pack1(float a){
    ull r; asm("mov.b64 %0, {%1,%1};" : "=l"(r) : "f"(a)); return r;
}
__device__ __forceinline__ void unpack2(ull v, float& a, float& b){
    asm("mov.b64 {%0,%1}, %2;" : "=f"(a), "=f"(b) : "l"(v));
}
__device__ __forceinline__ ull mul2(ull a, ull b){
    ull d; asm("mul.rn.f32x2 %0, %1, %2;" : "=l"(d) : "l"(a), "l"(b)); return d;
}
__device__ __forceinline__ ull fma2r(ull a, ull b, ull c){
    ull d; asm("fma.rn.f32x2 %0, %1, %2, %3;" : "=l"(d) : "l"(a), "l"(b), "l"(c)); return d;
}

// ---------------- weight repack ----------------
__global__ void repack_all(const float* __restrict__ w_in, const float* __restrict__ wq,
                           const float* __restrict__ wk,   const float* __restrict__ wv,
                           const float* __restrict__ w_i,  const float* __restrict__ w_g,
                           const float* __restrict__ w_o,  const float* __restrict__ w_out,
                           const float* __restrict__ w_conv)
{
    int idx = blockIdx.x*256 + threadIdx.x;
    if (idx < 5*16384) {
        int m = idx >> 14; int r = idx & 16383; int o = r >> 7; int i = r & 127;
        float v;
        if      (m==0) v = w_in[r];
        else if (m==1) v = wq[r];
        else if (m==2) v = wk[r];
        else if (m==3) v = wv[r];
        else           v = w_out[r];
        float* d = (m==0)?g_wt_in:(m==1)?g_wt_q:(m==2)?g_wt_k:(m==3)?g_wt_v:g_wt_out;
        d[i*128+o] = v;
    } else if (idx < 5*16384 + 3*32768) {
        int r = idx - 5*16384; int m = r >> 15; int rr = r & 32767;
        int o = rr >> 8; int i = rr & 255;    // src [128][256]
        float v = (m==0) ? w_i[rr] : (m==1) ? w_g[rr] : w_o[rr];
        float* d = (m==0)?g_wt_i:(m==1)?g_wt_g:g_wt_o;
        d[i*128+o] = v;
    } else if (idx < 5*16384 + 3*32768 + 147456) {
        int r = idx - (5*16384 + 3*32768);
        int o = r / 1152; int rem = r - o*1152;         // rem = ci*9+tap, ci<128
        g_wt_conv[rem*128 + o] = w_conv[(size_t)o*2304 + rem];
    }
}

// ---------------- in/out 128-in GEMM (double-buffered, f32x2) ----------------
// MODE 3: in-proj from x -> g_xtp padded, tanh, bias
// MODE 4: out-proj from g_h -> outx, bias
template<int MODE>
__global__ void gemm128_kernel(const float* __restrict__ inx,
                               const float* __restrict__ bias,
                               float* __restrict__ outx)
{
    __shared__ float xs[2][16][64];
    __shared__ float ws[2][16][128];
    const int n  = blockIdx.y;
    const int t0 = blockIdx.x * 64;
    const int tid = threadIdx.x;
    const int tt = tid & 15;       // token group (4 tokens)
    const int og = tid >> 4;       // out group (8 outs = 4 o-pairs)

    const float* in = (MODE==3) ? inx : g_h;
    const float* wt = (MODE==3) ? g_wt_in : g_wt_out;
    const float* xn = in + (size_t)n * 128 * HWTOK;

    ull acc2[4][4];
    #pragma unroll
    for (int p=0;p<4;p++) for (int t=0;t<4;t++) acc2[p][t] = 0ull;

    float xr[4]; float wr[8];
    #pragma unroll
    for (int r=0;r<4;r++){ int idx=tid+r*256, i=idx>>6, t=idx&63, gt=t0+t;
        xr[r] = (gt<HWTOK) ? xn[(size_t)i*HWTOK+gt] : 0.f; }
    #pragma unroll
    for (int r=0;r<8;r++){ int idx=tid+r*256, i=idx>>7, o=idx&127;
        wr[r] = wt[i*128+o]; }
    #pragma unroll
    for (int r=0;r<4;r++){ int idx=tid+r*256; xs[0][idx>>6][idx&63]=xr[r]; }
    #pragma unroll
    for (int r=0;r<8;r++){ int idx=tid+r*256; ws[0][idx>>7][idx&127]=wr[r]; }
    __syncthreads();

    for (int s=0; s<8; s++){
        const int b = s&1;
        if (s<7){
            const int kc=(s+1)*16;
            #pragma unroll
            for (int r=0;r<4;r++){ int idx=tid+r*256, i=idx>>6, t=idx&63, gt=t0+t;
                xr[r] = (gt<HWTOK) ? xn[(size_t)(kc+i)*HWTOK+gt] : 0.f; }
            #pragma unroll
            for (int r=0;r<8;r++){ int idx=tid+r*256, i=idx>>7, o=idx&127;
                wr[r] = wt[(kc+i)*128+o]; }
        }
        #pragma unroll
        for (int i=0;i<16;i++){
            float4 xv = *(const float4*)&xs[b][i][tt*4];
            ull xb[4] = {pack1(xv.x), pack1(xv.y), pack1(xv.z), pack1(xv.w)};
            ulonglong2 w0 = *(const ulonglong2*)&ws[b][i][og*8];
            ulonglong2 w1 = *(const ulonglong2*)&ws[b][i][og*8+4];
            ull wp[4] = {w0.x, w0.y, w1.x, w1.y};
            #pragma unroll
            for (int p=0;p<4;p++)
                #pragma unroll
                for (int t=0;t<4;t++)
                    acc2[p][t] = fma2r(xb[t], wp[p], acc2[p][t]);
        }
        if (s<7){
            const int nb = b^1;
            #pragma unroll
            for (int r=0;r<4;r++){ int idx=tid+r*256; xs[nb][idx>>6][idx&63]=xr[r]; }
            #pragma unroll
            for (int r=0;r<8;r++){ int idx=tid+r*256; ws[nb][idx>>7][idx&127]=wr[r]; }
        }
        __syncthreads();
    }

    #pragma unroll
    for (int p=0;p<4;p++){
        int oc0 = og*8 + 2*p;
        float b0 = bias[oc0], b1 = bias[oc0+1];
        #pragma unroll
        for (int t=0;t<4;t++){
            int gt = t0 + tt*4 + t;
            if (gt >= HWTOK) continue;
            float v0, v1; unpack2(acc2[p][t], v0, v1);
            v0 += b0; v1 += b1;
            if (MODE==3){
                int y = gt/WW, xc = gt - y*WW;
                size_t base = (((size_t)n*RCH)*HP + (y+1))*HP + (xc+1);
                g_xtp[base + (size_t)oc0*HP*HP]     = tanh_fast(v0);
                g_xtp[base + (size_t)(oc0+1)*HP*HP] = tanh_fast(v1);
            } else {
                outx[((size_t)n*RCH+oc0)*HWTOK+gt]   = v0;
                outx[((size_t)n*RCH+oc0+1)*HWTOK+gt] = v1;
            }
        }
    }
}

// ---------------- fused q/k/v GEMM (double-buffered) ----------------
__global__ void qkv_kernel()
{
    __shared__ float xs [2][16][32];
    __shared__ float wsq[2][16][128];
    __shared__ float wsk[2][16][128];
    __shared__ float wsv[2][16][128];
    const int n = blockIdx.y;
    const int t0 = blockIdx.x*32;
    const int tid = threadIdx.x;
    const int tt = tid & 7;      // 8 token groups x 4
    const int og = tid >> 3;     // 32 out groups x 4 (2 o-pairs)

    ull acc2[3][2][4];
    #pragma unroll
    for (int m=0;m<3;m++) for (int p=0;p<2;p++) for (int t=0;t<4;t++) acc2[m][p][t]=0ull;

    const float* in = g_za + (size_t)n*256*HWTOK;   // z region (first 128 ch)
    float xr[2]; float wrq[8], wrk[8], wrv[8];
    #pragma unroll
    for (int r=0;r<2;r++){ int idx=tid+r*256, i=idx>>5, t=idx&31, gt=t0+t;
        xr[r] = (gt<HWTOK) ? in[(size_t)i*HWTOK+gt] : 0.f; }
    #pragma unroll
    for (int r=0;r<8;r++){ int idx=tid+r*256, i=idx>>7, o=idx&127;
        wrq[r]=g_wt_q[i*128+o]; wrk[r]=g_wt_k[i*128+o]; wrv[r]=g_wt_v[i*128+o]; }
    #pragma unroll
    for (int r=0;r<2;r++){ int idx=tid+r*256; xs[0][idx>>5][idx&31]=xr[r]; }
    #pragma unroll
    for (int r=0;r<8;r++){ int idx=tid+r*256, i=idx>>7, o=idx&127;
        wsq[0][i][o]=wrq[r]; wsk[0][i][o]=wrk[r]; wsv[0][i][o]=wrv[r]; }
    __syncthreads();

    for (int s=0; s<8; s++){
        const int b = s&1;
        if (s<7){
            const int kc=(s+1)*16;
            #pragma unroll
            for (int r=0;r<2;r++){ int idx=tid+r*256, i=idx>>5, t=idx&31, gt=t0+t;
                xr[r] = (gt<HWTOK) ? in[(size_t)(kc+i)*HWTOK+gt] : 0.f; }
            #pragma unroll
            for (int r=0;r<8;r++){ int idx=tid+r*256, i=idx>>7, o=idx&127;
                wrq[r]=g_wt_q[(kc+i)*128+o]; wrk[r]=g_wt_k[(kc+i)*128+o]; wrv[r]=g_wt_v[(kc+i)*128+o]; }
        }
        #pragma unroll
        for (int i=0;i<16;i++){
            float4 xv = *(const float4*)&xs[b][i][tt*4];
            ull xb[4] = {pack1(xv.x), pack1(xv.y), pack1(xv.z), pack1(xv.w)};
            ulonglong2 wq2 = *(const ulonglong2*)&wsq[b][i][og*4];
            ulonglong2 wk2 = *(const ulonglong2*)&wsk[b][i][og*4];
            ulonglong2 wv2 = *(const ulonglong2*)&wsv[b][i][og*4];
            #pragma unroll
            for (int t=0;t<4;t++){
                acc2[0][0][t] = fma2r(xb[t], wq2.x, acc2[0][0][t]);
                acc2[0][1][t] = fma2r(xb[t], wq2.y, acc2[0][1][t]);
                acc2[1][0][t] = fma2r(xb[t], wk2.x, acc2[1][0][t]);
                acc2[1][1][t] = fma2r(xb[t], wk2.y, acc2[1][1][t]);
                acc2[2][0][t] = fma2r(xb[t], wv2.x, acc2[2][0][t]);
                acc2[2][1][t] = fma2r(xb[t], wv2.y, acc2[2][1][t]);
            }
        }
        if (s<7){
            const int nb = b^1;
            #pragma unroll
            for (int r=0;r<2;r++){ int idx=tid+r*256; xs[nb][idx>>5][idx&31]=xr[r]; }
            #pragma unroll
            for (int r=0;r<8;r++){ int idx=tid+r*256, i=idx>>7, o=idx&127;
                wsq[nb][i][o]=wrq[r]; wsk[nb][i][o]=wrk[r]; wsv[nb][i][o]=wrv[r]; }
        }
        __syncthreads();
    }

    #pragma unroll
    for (int m=0;m<3;m++){
        float* dst = (m==0)?g_q:(m==1)?g_k:g_v;
        #pragma unroll
        for (int p=0;p<2;p++){
            int oc0 = og*4 + 2*p;
            #pragma unroll
            for (int t=0;t<4;t++){
                int gt = t0 + tt*4 + t;
                if (gt >= HWTOK) continue;
                float v0, v1; unpack2(acc2[m][p][t], v0, v1);
                dst[((size_t)n*RCH+oc0)*HWTOK+gt]   = v0;
                dst[((size_t)n*RCH+oc0+1)*HWTOK+gt] = v1;
            }
        }
    }
}

// ---------------- conv3x3 (2 output rows/block, double-buffered) ----------------
__global__ void conv3x3_kernel(const float* __restrict__ bias)
{
    __shared__ float xs[2][8][4][40];   // 40-float rows for 16B-aligned float4 loads
    __shared__ float ws[2][8][9][128];
    const int n  = blockIdx.y;
    const int y0 = blockIdx.x*2;        // output rows y0,y0+1; padded input rows y0..y0+3
    const int tid = threadIdx.x;        // 288 threads
    const int tg = tid % 9;             // token group (4 cols)
    const int og = tid / 9;             // 0..31 (4 outs = 2 o-pairs)
    ull acc2[2][2][4];                  // [yrow][opair][tok]
    #pragma unroll
    for (int yr=0;yr<2;yr++) for (int p=0;p<2;p++) for (int t=0;t<4;t++) acc2[yr][p][t]=0ull;

    const float* xp = g_xtp + (size_t)n*RCH*HP*HP;
    float xr[5]; float4 wr[8];

    // prologue loads (kc=0)
    #pragma unroll
    for (int r=0;r<5;r++){
        int idx = tid + r*288;
        if (idx < 1216){
            int ci = idx/152, rem = idx - ci*152, dy = rem/38, cx = rem - dy*38;
            xr[r] = xp[(size_t)ci*HP*HP + (y0+dy)*HP + cx];
        }
    }
    #pragma unroll
    for (int r=0;r<8;r++) wr[r] = ((const float4*)g_wt_conv)[tid + r*288];
    #pragma unroll
    for (int r=0;r<5;r++){
        int idx = tid + r*288;
        if (idx < 1216){
            int ci = idx/152, rem = idx - ci*152, dy = rem/38, cx = rem - dy*38;
            xs[0][ci][dy][cx] = xr[r];
        }
    }
    #pragma unroll
    for (int r=0;r<8;r++) ((float4*)ws[0])[tid + r*288] = wr[r];
    __syncthreads();

    for (int s=0; s<16; s++){
        const int b = s&1;
        if (s<15){
            const int kc=(s+1)*8;
            #pragma unroll
            for (int r=0;r<5;r++){
                int idx = tid + r*288;
                if (idx < 1216){
                    int ci = idx/152, rem = idx - ci*152, dy = rem/38, cx = rem - dy*38;
                    xr[r] = xp[(size_t)(kc+ci)*HP*HP + (y0+dy)*HP + cx];
                }
            }
            #pragma unroll
            for (int r=0;r<8;r++) wr[r] = ((const float4*)(g_wt_conv + kc*1152))[tid + r*288];
        }
        #pragma unroll
        for (int i=0;i<8;i++){
            ull xb[4][6];
            #pragma unroll
            for (int dy=0; dy<4; dy++){
                float4 x4 = *(const float4*)&xs[b][i][dy][tg*4];
                float2 x2 = *(const float2*)&xs[b][i][dy][tg*4+4];
                xb[dy][0]=pack1(x4.x); xb[dy][1]=pack1(x4.y); xb[dy][2]=pack1(x4.z);
                xb[dy][3]=pack1(x4.w); xb[dy][4]=pack1(x2.x); xb[dy][5]=pack1(x2.y);
            }
            #pragma unroll
            for (int dy=0;dy<3;dy++)
                #pragma unroll
                for (int dx=0;dx<3;dx++){
                    ulonglong2 w2 = *(const ulonglong2*)&ws[b][i][dy*3+dx][og*4];
                    #pragma unroll
                    for (int yr=0;yr<2;yr++)
                        #pragma unroll
                        for (int t=0;t<4;t++){
                            acc2[yr][0][t] = fma2r(xb[dy+yr][t+dx], w2.x, acc2[yr][0][t]);
                            acc2[yr][1][t] = fma2r(xb[dy+yr][t+dx], w2.y, acc2[yr][1][t]);
                        }
                }
        }
        if (s<15){
            const int nb = b^1;
            #pragma unroll
            for (int r=0;r<5;r++){
                int idx = tid + r*288;
                if (idx < 1216){
                    int ci = idx/152, rem = idx - ci*152, dy = rem/38, cx = rem - dy*38;
                    xs[nb][ci][dy][cx] = xr[r];
                }
            }
            #pragma unroll
            for (int r=0;r<8;r++) ((float4*)ws[nb])[tid + r*288] = wr[r];
        }
        __syncthreads();
    }

    #pragma unroll
    for (int yr=0;yr<2;yr++){
        int y = y0 + yr;
        #pragma unroll
        for (int p=0;p<2;p++){
            int oc0 = og*4 + 2*p;
            float b0 = bias[oc0], b1 = bias[oc0+1];
            #pragma unroll
            for (int t=0;t<4;t++){
                int xc = tg*4+t;
                float v0, v1; unpack2(acc2[yr][p][t], v0, v1);
                g_za[((size_t)n*256 + oc0)*HWTOK + y*WW + xc]   = v0 + b0;
                g_za[((size_t)n*256 + oc0+1)*HWTOK + y*WW + xc] = v1 + b1;
            }
        }
    }
}

// ---------------- attention: K,V smem-resident, single wave, 3 q/thread ----------------
#define ATTN_THREADS 224
#define ATTN_ACT 216
#define ATTN_SMEM (2*HWTOK*HEADC*4)

__global__ void attn_kernel()
{
    extern __shared__ float sm[];
    float* Ks = sm;                       // [1296][16]
    float* Vs = sm + HWTOK*HEADC;
    const int nh = blockIdx.y; const int n = nh >> 3; const int h = nh & 7;
    const int tid = threadIdx.x;
    const float* kp = g_k + ((size_t)n*RCH + h*HEADC)*HWTOK;
    const float* vp = g_v + ((size_t)n*RCH + h*HEADC)*HWTOK;
    #pragma unroll
    for (int c=0;c<HEADC;c++){
        for (int j=tid;j<HWTOK;j+=ATTN_THREADS){
            Ks[j*HEADC+c] = kp[(size_t)c*HWTOK+j];
            Vs[j*HEADC+c] = vp[(size_t)c*HWTOK+j];
        }
    }
    __syncthreads();

    if (tid < ATTN_ACT){
        const int q0 = blockIdx.x*648 + tid;     // q0, q0+216, q0+432
        const float* qp = g_q + ((size_t)n*RCH + h*HEADC)*HWTOK;
        ull q2[3][8], a2[3][8]; float l[3];
        #pragma unroll
        for (int u=0;u<3;u++){
            int q = q0 + u*ATTN_ACT;
            #pragma unroll
            for (int p=0;p<8;p++){
                q2[u][p] = pack2(qp[(size_t)(2*p)*HWTOK+q]*LOG2E,
                                 qp[(size_t)(2*p+1)*HWTOK+q]*LOG2E);
                a2[u][p] = 0ull;
            }
            l[u] = 0.f;
        }
        #pragma unroll 2
        for (int j=0;j<HWTOK;j++){
            const ulonglong2* kr = (const ulonglong2*)(Ks + j*HEADC);
            ulonglong2 k0 = kr[0], k1 = kr[1], k2 = kr[2], k3 = kr[3];
            float e[3];
            #pragma unroll
            for (int u=0;u<3;u++){
                ull s = mul2(q2[u][0], k0.x);
                s = fma2r(q2[u][1], k0.y, s);
                s = fma2r(q2[u][2], k1.x, s);
                s = fma2r(q2[u][3], k1.y, s);
                s = fma2r(q2[u][4], k2.x, s);
                s = fma2r(q2[u][5], k2.y, s);
                s = fma2r(q2[u][6], k3.x, s);
                s = fma2r(q2[u][7], k3.y, s);
                float s0, s1; unpack2(s, s0, s1);
                e[u] = ex2_fast(s0 + s1);
                l[u] += e[u];
            }
            const ulonglong2* vr = (const ulonglong2*)(Vs + j*HEADC);
            ulonglong2 v0 = vr[0], v1 = vr[1], v2 = vr[2], v3 = vr[3];
            ull vv[8] = {v0.x,v0.y,v1.x,v1.y,v2.x,v2.y,v3.x,v3.y};
            #pragma unroll
            for (int u=0;u<3;u++){
                ull eb = pack1(e[u]);
                #pragma unroll
                for (int p=0;p<8;p++) a2[u][p] = fma2r(eb, vv[p], a2[u][p]);
            }
        }
        float* ap = g_za + ((size_t)n*256 + 128 + h*HEADC)*HWTOK;
        #pragma unroll
        for (int u=0;u<3;u++){
            int q = q0 + u*ATTN_ACT;
            float inv = 1.f / l[u];
            #pragma unroll
            for (int p=0;p<8;p++){
                float lo, hi; unpack2(a2[u][p], lo, hi);
                ap[(size_t)(2*p)*HWTOK + q]   = lo*inv;
                ap[(size_t)(2*p+1)*HWTOK + q] = hi*inv;
            }
        }
    }
}

// ---------------- fused gates i/g/o -> h (double-buffered; f*c0==0) ----------------
__global__ void gates_kernel(const float* __restrict__ bi,
                             const float* __restrict__ bg,
                             const float* __restrict__ bo)
{
    __shared__ float xs [2][16][32];
    __shared__ float wsi[2][16][128];
    __shared__ float wsg[2][16][128];
    __shared__ float wso[2][16][128];
    const int n = blockIdx.y;
    const int t0 = blockIdx.x*32;
    const int tid = threadIdx.x;
    const int tt = tid & 7;
    const int og = tid >> 3;
    ull ai[2][4], ag[2][4], ao[2][4];
    #pragma unroll
    for (int p=0;p<2;p++) for (int t=0;t<4;t++){ ai[p][t]=0ull; ag[p][t]=0ull; ao[p][t]=0ull; }

    const float* in = g_za + (size_t)n*256*HWTOK;
    float xr[2]; float wri[8], wrg[8], wro[8];
    #pragma unroll
    for (int r=0;r<2;r++){ int idx=tid+r*256, i=idx>>5, t=idx&31, gt=t0+t;
        xr[r] = (gt<HWTOK) ? in[(size_t)i*HWTOK+gt] : 0.f; }
    #pragma unroll
    for (int r=0;r<8;r++){ int idx=tid+r*256, i=idx>>7, o=idx&127;
        wri[r]=g_wt_i[i*128+o]; wrg[r]=g_wt_g[i*128+o]; wro[r]=g_wt_o[i*128+o]; }
    #pragma unroll
    for (int r=0;r<2;r++){ int idx=tid+r*256; xs[0][idx>>5][idx&31]=xr[r]; }
    #pragma unroll
    for (int r=0;r<8;r++){ int idx=tid+r*256, i=idx>>7, o=idx&127;
        wsi[0][i][o]=wri[r]; wsg[0][i][o]=wrg[r]; wso[0][i][o]=wro[r]; }
    __syncthreads();

    for (int s=0; s<16; s++){
        const int b = s&1;
        if (s<15){
            const int kc=(s+1)*16;
            #pragma unroll
            for (int r=0;r<2;r++){ int idx=tid+r*256, i=idx>>5, t=idx&31, gt=t0+t;
                xr[r] = (gt<HWTOK) ? in[(size_t)(kc+i)*HWTOK+gt] : 0.f; }
            #pragma unroll
            for (int r=0;r<8;r++){ int idx=tid+r*256, i=idx>>7, o=idx&127;
                wri[r]=g_wt_i[(kc+i)*128+o]; wrg[r]=g_wt_g[(kc+i)*128+o]; wro[r]=g_wt_o[(kc+i)*128+o]; }
        }
        #pragma unroll
        for (int i=0;i<16;i++){
            float4 xv = *(const float4*)&xs[b][i][tt*4];
            ull xb[4] = {pack1(xv.x), pack1(xv.y), pack1(xv.z), pack1(xv.w)};
            ulonglong2 wi2 = *(const ulonglong2*)&wsi[b][i][og*4];
            ulonglong2 wg2 = *(const ulonglong2*)&wsg[b][i][og*4];
            ulonglong2 wo2 = *(const ulonglong2*)&wso[b][i][og*4];
            #pragma unroll
            for (int t=0;t<4;t++){
                ai[0][t] = fma2r(xb[t], wi2.x, ai[0][t]);
                ai[1][t] = fma2r(xb[t], wi2.y, ai[1][t]);
                ag[0][t] = fma2r(xb[t], wg2.x, ag[0][t]);
                ag[1][t] = fma2r(xb[t], wg2.y, ag[1][t]);
                ao[0][t] = fma2r(xb[t], wo2.x, ao[0][t]);
                ao[1][t] = fma2r(xb[t], wo2.y, ao[1][t]);
            }
        }
        if (s<15){
            const int nb = b^1;
            #pragma unroll
            for (int r=0;r<2;r++){ int idx=tid+r*256; xs[nb][idx>>5][idx&31]=xr[r]; }
            #pragma unroll
            for (int r=0;r<8;r++){ int idx=tid+r*256, i=idx>>7, o=idx&127;
                wsi[nb][i][o]=wri[r]; wsg[nb][i][o]=wrg[r]; wso[nb][i][o]=wro[r]; }
        }
        __syncthreads();
    }

    #pragma unroll
    for (int p=0;p<2;p++){
        int oc0 = og*4 + 2*p;
        float bi0 = bi[oc0], bi1 = bi[oc0+1];
        float bg0 = bg[oc0], bg1 = bg[oc0+1];
        float bo0 = bo[oc0], bo1 = bo[oc0+1];
        #pragma unroll
        for (int t=0;t<4;t++){
            int gt = t0 + tt*4 + t;
            if (gt >= HWTOK) continue;
            float i0, i1, g0, g1, o0, o1;
            unpack2(ai[p][t], i0, i1);
            unpack2(ag[p][t], g0, g1);
            unpack2(ao[p][t], o0, o1);
            float iv0 = sigmoid_fast(i0 + bi0), iv1 = sigmoid_fast(i1 + bi1);
            float gv0 = tanh_fast(g0 + bg0),    gv1 = tanh_fast(g1 + bg1);
            float ov0 = sigmoid_fast(o0 + bo0), ov1 = sigmoid_fast(o1 + bo1);
            g_h[((size_t)n*RCH + oc0)*HWTOK + gt]   = ov0 * tanh_fast(iv0 * gv0);
            g_h[((size_t)n*RCH + oc0+1)*HWTOK + gt] = ov1 * tanh_fast(iv1 * gv1);
        }
    }
}

// ---------------- launch ----------------
extern "C" void kernel_launch(void* const* d_in, const int* in_sizes, int n_in,
                              void* d_out, int out_size)
{
    const float* x      = (const float*)d_in[0];
    const float* w_in   = (const float*)d_in[1];
    const float* b_in   = (const float*)d_in[2];
    const float* w_conv = (const float*)d_in[3];
    const float* b_conv = (const float*)d_in[4];
    const float* wq     = (const float*)d_in[5];
    const float* wk     = (const float*)d_in[6];
    const float* wv     = (const float*)d_in[7];
    const float* w_i    = (const float*)d_in[8];
    const float* b_i    = (const float*)d_in[9];
    // d_in[10], d_in[11]: w_f/b_f unused (first timestep: f*c0 == 0)
    const float* w_g    = (const float*)d_in[12];
    const float* b_g    = (const float*)d_in[13];
    const float* w_o    = (const float*)d_in[14];
    const float* b_o    = (const float*)d_in[15];
    const float* w_out  = (const float*)d_in[16];
    const float* b_out  = (const float*)d_in[17];
    float* out = (float*)d_out;

    cudaFuncSetAttribute(attn_kernel, cudaFuncAttributeMaxDynamicSharedMemorySize, ATTN_SMEM);

    repack_all<<<1280,256>>>(w_in, wq, wk, wv, w_i, w_g, w_o, w_out, w_conv);

    gemm128_kernel<3><<<dim3(21,NIMG),256>>>(x, b_in, nullptr);   // in-proj -> g_xtp
    conv3x3_kernel<<<dim3(18,NIMG),288>>>(b_conv);                // -> g_za[:, :128]
    qkv_kernel<<<dim3(41,NIMG),256>>>();                          // q,k,v
    attn_kernel<<<dim3(2, NIMG*NHEAD), ATTN_THREADS, ATTN_SMEM>>>(); // -> g_za[:,128:]
    gates_kernel<<<dim3(41,NIMG),256>>>(b_i, b_g, b_o);           // -> g_h
    gemm128_kernel<4><<<dim3(21,NIMG),256>>>(nullptr, b_out, out); // out-proj -> d_out
}

// round 4
// speedup vs baseline: 1.5671x; 1.0085x over previous
#include <cuda_runtime.h>
#include <math.h>

#define NIMG 8
#define HH 36
#define WW 36
#define HWTOK 1296
#define HP 38
#define RCH 128
#define NHEAD 8
#define HEADC 16
#define LOG2E 1.44269504088896340736f

typedef unsigned long long ull;

// ---------------- scratch (device globals; zero-init at load) ----------------
__device__ float g_xtp[(size_t)NIMG*RCH*HP*HP];     // padded tanh(in-proj); borders stay 0
__device__ float g_za [(size_t)NIMG*256*HWTOK];     // [z | a]
__device__ float g_q  [(size_t)NIMG*RCH*HWTOK];
__device__ float g_k  [(size_t)NIMG*RCH*HWTOK];
__device__ float g_v  [(size_t)NIMG*RCH*HWTOK];
__device__ float g_h  [(size_t)NIMG*RCH*HWTOK];
__device__ float g_pre[3][(size_t)NIMG*RCH*HWTOK];  // gate pre-activations i,g,o

// transposed weights ([in][out], coalesced for GEMM smem fills)
__device__ float g_wt_in [128*128];
__device__ float g_wt_q  [128*128];
__device__ float g_wt_k  [128*128];
__device__ float g_wt_v  [128*128];
__device__ float g_wt_out[128*128];
__device__ float g_wt_i  [256*128];
__device__ float g_wt_g  [256*128];
__device__ float g_wt_o  [256*128];
__device__ float g_wt_conv[1152*128];               // [(ci*9+tap)][o], ci<128 only

// ---------------- helpers ----------------
__device__ __forceinline__ float tanh_fast(float x){
    float r; asm("tanh.approx.f32 %0, %1;" : "=f"(r) : "f"(x)); return r;
}
__device__ __forceinline__ float sigmoid_fast(float x){
    return 0.5f * tanh_fast(0.5f * x) + 0.5f;
}
__device__ __forceinline__ float ex2_fast(float x){
    float r; asm("ex2.approx.f32 %0, %1;" : "=f"(r) : "f"(x)); return r;
}
__device__ __forceinline__ ull pack2(float a, float b){
    ull r; asm("mov.b64 %0, {%1,%2};" : "=l"(r) : "f"(a), "f"(b)); return r;
}
__device__ __forceinline__ ull pack1(float a){
    ull r; asm("mov.b64 %0, {%1,%1};" : "=l"(r) : "f"(a)); return r;
}
__device__ __forceinline__ void unpack2(ull v, float& a, float& b){
    asm("mov.b64 {%0,%1}, %2;" : "=f"(a), "=f"(b) : "l"(v));
}
__device__ __forceinline__ ull mul2(ull a, ull b){
    ull d; asm("mul.rn.f32x2 %0, %1, %2;" : "=l"(d) : "l"(a), "l"(b)); return d;
}
__device__ __forceinline__ ull fma2r(ull a, ull b, ull c){
    ull d; asm("fma.rn.f32x2 %0, %1, %2, %3;" : "=l"(d) : "l"(a), "l"(b), "l"(c)); return d;
}

// ---------------- weight repack ----------------
__global__ void repack_all(const float* __restrict__ w_in, const float* __restrict__ wq,
                           const float* __restrict__ wk,   const float* __restrict__ wv,
                           const float* __restrict__ w_i,  const float* __restrict__ w_g,
                           const float* __restrict__ w_o,  const float* __restrict__ w_out,
                           const float* __restrict__ w_conv)
{
    int idx = blockIdx.x*256 + threadIdx.x;
    if (idx < 5*16384) {
        int m = idx >> 14; int r = idx & 16383; int o = r >> 7; int i = r & 127;
        float v;
        if      (m==0) v = w_in[r];
        else if (m==1) v = wq[r];
        else if (m==2) v = wk[r];
        else if (m==3) v = wv[r];
        else           v = w_out[r];
        float* d = (m==0)?g_wt_in:(m==1)?g_wt_q:(m==2)?g_wt_k:(m==3)?g_wt_v:g_wt_out;
        d[i*128+o] = v;
    } else if (idx < 5*16384 + 3*32768) {
        int r = idx - 5*16384; int m = r >> 15; int rr = r & 32767;
        int o = rr >> 8; int i = rr & 255;    // src [128][256]
        float v = (m==0) ? w_i[rr] : (m==1) ? w_g[rr] : w_o[rr];
        float* d = (m==0)?g_wt_i:(m==1)?g_wt_g:g_wt_o;
        d[i*128+o] = v;
    } else if (idx < 5*16384 + 3*32768 + 147456) {
        int r = idx - (5*16384 + 3*32768);
        int o = r / 1152; int rem = r - o*1152;         // rem = ci*9+tap, ci<128
        g_wt_conv[rem*128 + o] = w_conv[(size_t)o*2304 + rem];
    }
}

// ---------------- lean GEMM core: 64 tok x 128 out, double-buffered ----------------
template<int KSTEPS>
__device__ __forceinline__ void gemm_core(const float* __restrict__ xn,
                                          const float* __restrict__ wt,
                                          int t0, ull (&acc2)[4][4],
                                          float (*xs)[16][64], float (*ws)[16][128])
{
    const int tid = threadIdx.x;
    const int tt = tid & 15;
    const int og = tid >> 4;
    float xr[4], wr[8];
    #pragma unroll
    for (int r=0;r<4;r++){ int idx=tid+r*256, i=idx>>6, t=idx&63, gt=t0+t;
        xr[r] = (gt<HWTOK) ? xn[(size_t)i*HWTOK+gt] : 0.f; }
    #pragma unroll
    for (int r=0;r<8;r++){ int idx=tid+r*256, i=idx>>7, o=idx&127;
        wr[r] = wt[i*128+o]; }
    #pragma unroll
    for (int r=0;r<4;r++){ int idx=tid+r*256; xs[0][idx>>6][idx&63]=xr[r]; }
    #pragma unroll
    for (int r=0;r<8;r++){ int idx=tid+r*256; ws[0][idx>>7][idx&127]=wr[r]; }
    __syncthreads();

    for (int s=0; s<KSTEPS; s++){
        const int b = s&1;
        if (s<KSTEPS-1){
            const int kc=(s+1)*16;
            #pragma unroll
            for (int r=0;r<4;r++){ int idx=tid+r*256, i=idx>>6, t=idx&63, gt=t0+t;
                xr[r] = (gt<HWTOK) ? xn[(size_t)(kc+i)*HWTOK+gt] : 0.f; }
            #pragma unroll
            for (int r=0;r<8;r++){ int idx=tid+r*256, i=idx>>7, o=idx&127;
                wr[r] = wt[(kc+i)*128+o]; }
        }
        #pragma unroll
        for (int i=0;i<16;i++){
            float4 xv = *(const float4*)&xs[b][i][tt*4];
            ull xb[4] = {pack1(xv.x), pack1(xv.y), pack1(xv.z), pack1(xv.w)};
            ulonglong2 w0 = *(const ulonglong2*)&ws[b][i][og*8];
            ulonglong2 w1 = *(const ulonglong2*)&ws[b][i][og*8+4];
            ull wp[4] = {w0.x, w0.y, w1.x, w1.y};
            #pragma unroll
            for (int p=0;p<4;p++)
                #pragma unroll
                for (int t=0;t<4;t++)
                    acc2[p][t] = fma2r(xb[t], wp[p], acc2[p][t]);
        }
        if (s<KSTEPS-1){
            const int nb = b^1;
            #pragma unroll
            for (int r=0;r<4;r++){ int idx=tid+r*256; xs[nb][idx>>6][idx&63]=xr[r]; }
            #pragma unroll
            for (int r=0;r<8;r++){ int idx=tid+r*256; ws[nb][idx>>7][idx&127]=wr[r]; }
        }
        __syncthreads();
    }
}

// ---------------- in-proj: x -> tanh -> padded g_xtp ----------------
__global__ __launch_bounds__(256) void inproj_kernel(const float* __restrict__ x,
                                                     const float* __restrict__ bias)
{
    __shared__ float xs[2][16][64];
    __shared__ float ws[2][16][128];
    const int n  = blockIdx.y;
    const int t0 = blockIdx.x * 64;
    const int tt = threadIdx.x & 15;
    const int og = threadIdx.x >> 4;
    ull acc2[4][4];
    #pragma unroll
    for (int p=0;p<4;p++) for (int t=0;t<4;t++) acc2[p][t] = 0ull;
    gemm_core<8>(x + (size_t)n*128*HWTOK, g_wt_in, t0, acc2, xs, ws);
    #pragma unroll
    for (int p=0;p<4;p++){
        int oc0 = og*8 + 2*p;
        float b0 = bias[oc0], b1 = bias[oc0+1];
        #pragma unroll
        for (int t=0;t<4;t++){
            int gt = t0 + tt*4 + t;
            if (gt >= HWTOK) continue;
            float v0, v1; unpack2(acc2[p][t], v0, v1);
            int y = gt/WW, xc = gt - y*WW;
            size_t base = (((size_t)n*RCH)*HP + (y+1))*HP + (xc+1);
            g_xtp[base + (size_t)oc0*HP*HP]     = tanh_fast(v0 + b0);
            g_xtp[base + (size_t)(oc0+1)*HP*HP] = tanh_fast(v1 + b1);
        }
    }
}

// ---------------- qkv: z selects matrix; raw store ----------------
__global__ __launch_bounds__(256) void qkv_kernel()
{
    __shared__ float xs[2][16][64];
    __shared__ float ws[2][16][128];
    const int n  = blockIdx.y;
    const int z  = blockIdx.z;
    const int t0 = blockIdx.x * 64;
    const int tt = threadIdx.x & 15;
    const int og = threadIdx.x >> 4;
    const float* wt = (z==0) ? g_wt_q : (z==1) ? g_wt_k : g_wt_v;
    float* dst      = (z==0) ? g_q    : (z==1) ? g_k    : g_v;
    ull acc2[4][4];
    #pragma unroll
    for (int p=0;p<4;p++) for (int t=0;t<4;t++) acc2[p][t] = 0ull;
    gemm_core<8>(g_za + (size_t)n*256*HWTOK, wt, t0, acc2, xs, ws);
    #pragma unroll
    for (int p=0;p<4;p++){
        int oc0 = og*8 + 2*p;
        #pragma unroll
        for (int t=0;t<4;t++){
            int gt = t0 + tt*4 + t;
            if (gt >= HWTOK) continue;
            float v0, v1; unpack2(acc2[p][t], v0, v1);
            dst[((size_t)n*RCH+oc0)*HWTOK+gt]   = v0;
            dst[((size_t)n*RCH+oc0+1)*HWTOK+gt] = v1;
        }
    }
}

// ---------------- gates GEMM: z in {i,g,o}; raw store to g_pre ----------------
__global__ __launch_bounds__(256) void gates_gemm_kernel()
{
    __shared__ float xs[2][16][64];
    __shared__ float ws[2][16][128];
    const int n  = blockIdx.y;
    const int z  = blockIdx.z;
    const int t0 = blockIdx.x * 64;
    const int tt = threadIdx.x & 15;
    const int og = threadIdx.x >> 4;
    const float* wt = (z==0) ? g_wt_i : (z==1) ? g_wt_g : g_wt_o;
    float* dst = g_pre[z];
    ull acc2[4][4];
    #pragma unroll
    for (int p=0;p<4;p++) for (int t=0;t<4;t++) acc2[p][t] = 0ull;
    gemm_core<16>(g_za + (size_t)n*256*HWTOK, wt, t0, acc2, xs, ws);
    #pragma unroll
    for (int p=0;p<4;p++){
        int oc0 = og*8 + 2*p;
        #pragma unroll
        for (int t=0;t<4;t++){
            int gt = t0 + tt*4 + t;
            if (gt >= HWTOK) continue;
            float v0, v1; unpack2(acc2[p][t], v0, v1);
            dst[((size_t)n*RCH+oc0)*HWTOK+gt]   = v0;
            dst[((size_t)n*RCH+oc0+1)*HWTOK+gt] = v1;
        }
    }
}

// ---------------- LSTM activation: h = sigm(o) * tanh(sigm(i)*tanh(g)) ----------------
#define ACT_N4 (NIMG*RCH*(HWTOK/4))
__global__ __launch_bounds__(256) void lstm_act_kernel(const float* __restrict__ bi,
                                                       const float* __restrict__ bg,
                                                       const float* __restrict__ bo)
{
    int i4 = blockIdx.x*256 + threadIdx.x;
    if (i4 >= ACT_N4) return;
    int oc = (i4 / (HWTOK/4)) & 127;
    float bbi = bi[oc], bbg = bg[oc], bbo = bo[oc];
    float4 pi = ((const float4*)g_pre[0])[i4];
    float4 pg = ((const float4*)g_pre[1])[i4];
    float4 po = ((const float4*)g_pre[2])[i4];
    float4 r;
    r.x = sigmoid_fast(po.x+bbo) * tanh_fast(sigmoid_fast(pi.x+bbi) * tanh_fast(pg.x+bbg));
    r.y = sigmoid_fast(po.y+bbo) * tanh_fast(sigmoid_fast(pi.y+bbi) * tanh_fast(pg.y+bbg));
    r.z = sigmoid_fast(po.z+bbo) * tanh_fast(sigmoid_fast(pi.z+bbi) * tanh_fast(pg.z+bbg));
    r.w = sigmoid_fast(po.w+bbo) * tanh_fast(sigmoid_fast(pi.w+bbi) * tanh_fast(pg.w+bbg));
    ((float4*)g_h)[i4] = r;
}

// ---------------- out-proj ----------------
__global__ __launch_bounds__(256) void outproj_kernel(const float* __restrict__ bias,
                                                      float* __restrict__ outx)
{
    __shared__ float xs[2][16][64];
    __shared__ float ws[2][16][128];
    const int n  = blockIdx.y;
    const int t0 = blockIdx.x * 64;
    const int tt = threadIdx.x & 15;
    const int og = threadIdx.x >> 4;
    ull acc2[4][4];
    #pragma unroll
    for (int p=0;p<4;p++) for (int t=0;t<4;t++) acc2[p][t] = 0ull;
    gemm_core<8>(g_h + (size_t)n*128*HWTOK, g_wt_out, t0, acc2, xs, ws);
    #pragma unroll
    for (int p=0;p<4;p++){
        int oc0 = og*8 + 2*p;
        float b0 = bias[oc0], b1 = bias[oc0+1];
        #pragma unroll
        for (int t=0;t<4;t++){
            int gt = t0 + tt*4 + t;
            if (gt >= HWTOK) continue;
            float v0, v1; unpack2(acc2[p][t], v0, v1);
            outx[((size_t)n*RCH+oc0)*HWTOK+gt]   = v0 + b0;
            outx[((size_t)n*RCH+oc0+1)*HWTOK+gt] = v1 + b1;
        }
    }
}

// ---------------- conv3x3 (2 output rows/block, double-buffered) ----------------
__global__ void conv3x3_kernel(const float* __restrict__ bias)
{
    __shared__ float xs[2][8][4][40];
    __shared__ float ws[2][8][9][128];
    const int n  = blockIdx.y;
    const int y0 = blockIdx.x*2;
    const int tid = threadIdx.x;        // 288 threads
    const int tg = tid % 9;
    const int og = tid / 9;
    ull acc2[2][2][4];
    #pragma unroll
    for (int yr=0;yr<2;yr++) for (int p=0;p<2;p++) for (int t=0;t<4;t++) acc2[yr][p][t]=0ull;

    const float* xp = g_xtp + (size_t)n*RCH*HP*HP;
    float xr[5]; float4 wr[8];

    #pragma unroll
    for (int r=0;r<5;r++){
        int idx = tid + r*288;
        if (idx < 1216){
            int ci = idx/152, rem = idx - ci*152, dy = rem/38, cx = rem - dy*38;
            xr[r] = xp[(size_t)ci*HP*HP + (y0+dy)*HP + cx];
        }
    }
    #pragma unroll
    for (int r=0;r<8;r++) wr[r] = ((const float4*)g_wt_conv)[tid + r*288];
    #pragma unroll
    for (int r=0;r<5;r++){
        int idx = tid + r*288;
        if (idx < 1216){
            int ci = idx/152, rem = idx - ci*152, dy = rem/38, cx = rem - dy*38;
            xs[0][ci][dy][cx] = xr[r];
        }
    }
    #pragma unroll
    for (int r=0;r<8;r++) ((float4*)ws[0])[tid + r*288] = wr[r];
    __syncthreads();

    for (int s=0; s<16; s++){
        const int b = s&1;
        if (s<15){
            const int kc=(s+1)*8;
            #pragma unroll
            for (int r=0;r<5;r++){
                int idx = tid + r*288;
                if (idx < 1216){
                    int ci = idx/152, rem = idx - ci*152, dy = rem/38, cx = rem - dy*38;
                    xr[r] = xp[(size_t)(kc+ci)*HP*HP + (y0+dy)*HP + cx];
                }
            }
            #pragma unroll
            for (int r=0;r<8;r++) wr[r] = ((const float4*)(g_wt_conv + kc*1152))[tid + r*288];
        }
        #pragma unroll
        for (int i=0;i<8;i++){
            ull xb[4][6];
            #pragma unroll
            for (int dy=0; dy<4; dy++){
                float4 x4 = *(const float4*)&xs[b][i][dy][tg*4];
                float2 x2 = *(const float2*)&xs[b][i][dy][tg*4+4];
                xb[dy][0]=pack1(x4.x); xb[dy][1]=pack1(x4.y); xb[dy][2]=pack1(x4.z);
                xb[dy][3]=pack1(x4.w); xb[dy][4]=pack1(x2.x); xb[dy][5]=pack1(x2.y);
            }
            #pragma unroll
            for (int dy=0;dy<3;dy++)
                #pragma unroll
                for (int dx=0;dx<3;dx++){
                    ulonglong2 w2 = *(const ulonglong2*)&ws[b][i][dy*3+dx][og*4];
                    #pragma unroll
                    for (int yr=0;yr<2;yr++)
                        #pragma unroll
                        for (int t=0;t<4;t++){
                            acc2[yr][0][t] = fma2r(xb[dy+yr][t+dx], w2.x, acc2[yr][0][t]);
                            acc2[yr][1][t] = fma2r(xb[dy+yr][t+dx], w2.y, acc2[yr][1][t]);
                        }
                }
        }
        if (s<15){
            const int nb = b^1;
            #pragma unroll
            for (int r=0;r<5;r++){
                int idx = tid + r*288;
                if (idx < 1216){
                    int ci = idx/152, rem = idx - ci*152, dy = rem/38, cx = rem - dy*38;
                    xs[nb][ci][dy][cx] = xr[r];
                }
            }
            #pragma unroll
            for (int r=0;r<8;r++) ((float4*)ws[nb])[tid + r*288] = wr[r];
        }
        __syncthreads();
    }

    #pragma unroll
    for (int yr=0;yr<2;yr++){
        int y = y0 + yr;
        #pragma unroll
        for (int p=0;p<2;p++){
            int oc0 = og*4 + 2*p;
            float b0 = bias[oc0], b1 = bias[oc0+1];
            #pragma unroll
            for (int t=0;t<4;t++){
                int xc = tg*4+t;
                float v0, v1; unpack2(acc2[yr][p][t], v0, v1);
                g_za[((size_t)n*256 + oc0)*HWTOK + y*WW + xc]   = v0 + b0;
                g_za[((size_t)n*256 + oc0+1)*HWTOK + y*WW + xc] = v1 + b1;
            }
        }
    }
}

// ---------------- attention: K,V smem-resident, 11 warps, 2 q/thread ----------------
#define ATTN_THREADS 352
#define ATTN_ACT 324
#define ATTN_SMEM (2*HWTOK*HEADC*4)

__global__ void attn_kernel()
{
    extern __shared__ float sm[];
    float* Ks = sm;                       // [1296][16]
    float* Vs = sm + HWTOK*HEADC;
    const int nh = blockIdx.y; const int n = nh >> 3; const int h = nh & 7;
    const int tid = threadIdx.x;
    const float* kp = g_k + ((size_t)n*RCH + h*HEADC)*HWTOK;
    const float* vp = g_v + ((size_t)n*RCH + h*HEADC)*HWTOK;
    #pragma unroll
    for (int c=0;c<HEADC;c++){
        for (int j=tid;j<HWTOK;j+=ATTN_THREADS){
            Ks[j*HEADC+c] = kp[(size_t)c*HWTOK+j];
            Vs[j*HEADC+c] = vp[(size_t)c*HWTOK+j];
        }
    }
    __syncthreads();

    if (tid < ATTN_ACT){
        const int q0 = blockIdx.x*648 + tid;     // q0, q0+324
        const float* qp = g_q + ((size_t)n*RCH + h*HEADC)*HWTOK;
        ull q2[2][8], a2[2][8]; float l[2];
        #pragma unroll
        for (int u=0;u<2;u++){
            int q = q0 + u*ATTN_ACT;
            #pragma unroll
            for (int p=0;p<8;p++){
                q2[u][p] = pack2(qp[(size_t)(2*p)*HWTOK+q]*LOG2E,
                                 qp[(size_t)(2*p+1)*HWTOK+q]*LOG2E);
                a2[u][p] = 0ull;
            }
            l[u] = 0.f;
        }
        #pragma unroll 2
        for (int j=0;j<HWTOK;j++){
            const ulonglong2* kr = (const ulonglong2*)(Ks + j*HEADC);
            ulonglong2 k0 = kr[0], k1 = kr[1], k2 = kr[2], k3 = kr[3];
            float e[2];
            #pragma unroll
            for (int u=0;u<2;u++){
                ull s = mul2(q2[u][0], k0.x);
                s = fma2r(q2[u][1], k0.y, s);
                s = fma2r(q2[u][2], k1.x, s);
                s = fma2r(q2[u][3], k1.y, s);
                s = fma2r(q2[u][4], k2.x, s);
                s = fma2r(q2[u][5], k2.y, s);
                s = fma2r(q2[u][6], k3.x, s);
                s = fma2r(q2[u][7], k3.y, s);
                float s0, s1; unpack2(s, s0, s1);
                e[u] = ex2_fast(s0 + s1);
                l[u] += e[u];
            }
            const ulonglong2* vr = (const ulonglong2*)(Vs + j*HEADC);
            ulonglong2 v0 = vr[0], v1 = vr[1], v2 = vr[2], v3 = vr[3];
            ull vv[8] = {v0.x,v0.y,v1.x,v1.y,v2.x,v2.y,v3.x,v3.y};
            #pragma unroll
            for (int u=0;u<2;u++){
                ull eb = pack1(e[u]);
                #pragma unroll
                for (int p=0;p<8;p++) a2[u][p] = fma2r(eb, vv[p], a2[u][p]);
            }
        }
        float* ap = g_za + ((size_t)n*256 + 128 + h*HEADC)*HWTOK;
        #pragma unroll
        for (int u=0;u<2;u++){
            int q = q0 + u*ATTN_ACT;
            float inv = 1.f / l[u];
            #pragma unroll
            for (int p=0;p<8;p++){
                float lo, hi; unpack2(a2[u][p], lo, hi);
                ap[(size_t)(2*p)*HWTOK + q]   = lo*inv;
                ap[(size_t)(2*p+1)*HWTOK + q] = hi*inv;
            }
        }
    }
}

// ---------------- launch ----------------
extern "C" void kernel_launch(void* const* d_in, const int* in_sizes, int n_in,
                              void* d_out, int out_size)
{
    const float* x      = (const float*)d_in[0];
    const float* w_in   = (const float*)d_in[1];
    const float* b_in   = (const float*)d_in[2];
    const float* w_conv = (const float*)d_in[3];
    const float* b_conv = (const float*)d_in[4];
    const float* wq     = (const float*)d_in[5];
    const float* wk     = (const float*)d_in[6];
    const float* wv     = (const float*)d_in[7];
    const float* w_i    = (const float*)d_in[8];
    const float* b_i    = (const float*)d_in[9];
    // d_in[10], d_in[11]: w_f/b_f unused (first timestep: f*c0 == 0)
    const float* w_g    = (const float*)d_in[12];
    const float* b_g    = (const float*)d_in[13];
    const float* w_o    = (const float*)d_in[14];
    const float* b_o    = (const float*)d_in[15];
    const float* w_out  = (const float*)d_in[16];
    const float* b_out  = (const float*)d_in[17];
    float* out = (float*)d_out;

    cudaFuncSetAttribute(attn_kernel, cudaFuncAttributeMaxDynamicSharedMemorySize, ATTN_SMEM);

    repack_all<<<1280,256>>>(w_in, wq, wk, wv, w_i, w_g, w_o, w_out, w_conv);

    inproj_kernel<<<dim3(21,NIMG),256>>>(x, b_in);                 // -> g_xtp
    conv3x3_kernel<<<dim3(18,NIMG),288>>>(b_conv);                 // -> g_za[:, :128]
    qkv_kernel<<<dim3(21,NIMG,3),256>>>();                         // -> g_q/g_k/g_v
    attn_kernel<<<dim3(2, NIMG*NHEAD), ATTN_THREADS, ATTN_SMEM>>>(); // -> g_za[:,128:]
    gates_gemm_kernel<<<dim3(21,NIMG,3),256>>>();                  // -> g_pre
    lstm_act_kernel<<<(ACT_N4+255)/256,256>>>(b_i, b_g, b_o);      // -> g_h
    outproj_kernel<<<dim3(21,NIMG),256>>>(b_out, out);             // -> d_out
}